// round 16
// baseline (speedup 1.0000x reference)
#include <cuda_runtime.h>
#include <cuda_bf16.h>
#include <mma.h>
#include <cstdint>

using namespace nvcuda;

// ---------------------------------------------------------------------------
// Stochastic_encoder (VGAE GCN encoder), bf16 split-precision wmma GEMMs,
// cp.async double-buffered mainloop, forked capture graph:
//   stream B: split_w, CSR build (zero/count/scan/fill + dinv)
//   default : split(x), GEMM1 (raw x@W1)
//   join    : agg1 (applies dinv weights) -> agg2 -> GEMM2 -> d_out
// Agg gather loops unrolled x4 for MLP.
// ---------------------------------------------------------------------------

#define NMAX   50176
#define EMAX   800000
#define HDIM   128
#define SCAN_B 1024
#define A_PITCH 40
#define B_PITCH 136
#define ASZ (128 * A_PITCH)   // 5120 bf16 per A buffer
#define BSZ (32 * B_PITCH)    // 4352 bf16 per B buffer
#define GEMM_SMEM ((4 * ASZ + 4 * BSZ) * 2)   // 75776 bytes

__device__ int   g_deg   [NMAX];
__device__ int   g_base  [NMAX];
__device__ int   g_cursor[NMAX];
__device__ int   g_part  [256];
__device__ int   g_adj   [EMAX];
__device__ float g_dinv  [NMAX];
__device__ float g_ts1   [(size_t)NMAX * HDIM];
__device__ float g_hsc   [(size_t)NMAX * HDIM];

__device__ __nv_bfloat16 g_ah[(size_t)NMAX * 256];
__device__ __nv_bfloat16 g_al[(size_t)NMAX * 256];
__device__ __nv_bfloat16 g_wh[512 * 128];   // W1 @0 (256 rows), Wmu @256, Wls @384
__device__ __nv_bfloat16 g_wl[512 * 128];

// --- cp.async helpers ------------------------------------------------------
__device__ __forceinline__ void cp16(uint32_t sdst, const void* gsrc) {
    asm volatile("cp.async.cg.shared.global [%0], [%1], 16;"
                 :: "r"(sdst), "l"(gsrc));
}
#define CP_COMMIT()   asm volatile("cp.async.commit_group;" ::: "memory")
#define CP_WAIT_ALL() asm volatile("cp.async.wait_group 0;" ::: "memory")

// ---------------------------------------------------------------------------

__global__ void k_zero_int(int* __restrict__ p, int n) {
    int i = blockIdx.x * blockDim.x + threadIdx.x;
    if (i < n) p[i] = 0;
}

__global__ void k_count(const int* __restrict__ dst, int* __restrict__ deg, int E) {
    int i = blockIdx.x * blockDim.x + threadIdx.x;
    if (i < E) atomicAdd(&deg[dst[i]], 1);
}

__global__ void k_scan_block(const int* __restrict__ deg, int* __restrict__ base,
                             int* __restrict__ part, int n)
{
    __shared__ int sh[SCAN_B];
    int gi = blockIdx.x * SCAN_B + threadIdx.x;
    int v = (gi < n) ? deg[gi] : 0;
    sh[threadIdx.x] = v;
    __syncthreads();
    #pragma unroll
    for (int off = 1; off < SCAN_B; off <<= 1) {
        int t = (threadIdx.x >= off) ? sh[threadIdx.x - off] : 0;
        __syncthreads();
        sh[threadIdx.x] += t;
        __syncthreads();
    }
    if (gi < n) base[gi] = sh[threadIdx.x] - v;
    if (threadIdx.x == SCAN_B - 1) part[blockIdx.x] = sh[threadIdx.x];
}

__global__ void k_scan_part(int* __restrict__ part, int nb) {
    __shared__ int sh[64];
    int i = threadIdx.x;
    int v = (i < nb) ? part[i] : 0;
    sh[i] = v;
    __syncthreads();
    #pragma unroll
    for (int off = 1; off < 64; off <<= 1) {
        int t = (i >= off) ? sh[i - off] : 0;
        __syncthreads();
        sh[i] += t;
        __syncthreads();
    }
    if (i < nb) part[i] = sh[i] - v;   // exclusive
}

__global__ void k_scan_add(int* __restrict__ base, int* __restrict__ cursor,
                           const int* __restrict__ part,
                           const int* __restrict__ deg,
                           float* __restrict__ dinv, int n) {
    int gi = blockIdx.x * SCAN_B + threadIdx.x;
    if (gi < n) {
        int b = base[gi] + part[blockIdx.x];
        base[gi]   = b;
        cursor[gi] = b;
        dinv[gi]   = rsqrtf((float)deg[gi] + 1.0f);
    }
}

__global__ void k_fill(const int* __restrict__ src, const int* __restrict__ dst,
                       int* __restrict__ cursor, int* __restrict__ adj, int E)
{
    int i = blockIdx.x * blockDim.x + threadIdx.x;
    if (i < E) {
        int pos = atomicAdd(&cursor[dst[i]], 1);
        adj[pos] = src[i];
    }
}

// ---------------------------------------------------------------------------
// fp32 -> bf16 (hi, lo) split, vectorized x4.
// ---------------------------------------------------------------------------
__device__ __forceinline__ void split_store(float4 v,
                                            __nv_bfloat16* hi,
                                            __nv_bfloat16* lo, int i)
{
    __nv_bfloat16 hx = __float2bfloat16(v.x);
    __nv_bfloat16 hy = __float2bfloat16(v.y);
    __nv_bfloat16 hz = __float2bfloat16(v.z);
    __nv_bfloat16 hw = __float2bfloat16(v.w);
    __nv_bfloat162* hp = (__nv_bfloat162*)hi;
    __nv_bfloat162* lp = (__nv_bfloat162*)lo;
    hp[2 * i]     = __nv_bfloat162(hx, hy);
    hp[2 * i + 1] = __nv_bfloat162(hz, hw);
    lp[2 * i]     = __nv_bfloat162(__float2bfloat16(v.x - __bfloat162float(hx)),
                                   __float2bfloat16(v.y - __bfloat162float(hy)));
    lp[2 * i + 1] = __nv_bfloat162(__float2bfloat16(v.z - __bfloat162float(hz)),
                                   __float2bfloat16(v.w - __bfloat162float(hw)));
}

__global__ void k_split(const float* __restrict__ src,
                        __nv_bfloat16* __restrict__ hi,
                        __nv_bfloat16* __restrict__ lo, int n4)
{
    int i = blockIdx.x * blockDim.x + threadIdx.x;
    if (i < n4) split_store(((const float4*)src)[i], hi, lo, i);
}

__global__ void k_split_w(const float* __restrict__ W1,
                          const float* __restrict__ Wmu,
                          const float* __restrict__ Wls,
                          __nv_bfloat16* __restrict__ wh,
                          __nv_bfloat16* __restrict__ wl)
{
    int i = blockIdx.x * blockDim.x + threadIdx.x;   // float4 index, < 16384
    if (i < 8192) {
        split_store(((const float4*)W1)[i], wh, wl, i);
    } else if (i < 12288) {
        int j = i - 8192;
        split_store(((const float4*)Wmu)[j], wh + 256 * 128, wl + 256 * 128, j);
    } else if (i < 16384) {
        int j = i - 12288;
        split_store(((const float4*)Wls)[j], wh + 384 * 128, wl + 384 * 128, j);
    }
}

// ---------------------------------------------------------------------------
// bf16 split-precision wmma GEMM, cp.async double-buffered.
//   C = Ah*Wh + Al*Wh + Ah*Wl (fp32 accum)
// mode 1: out = C + bias[c]   mode 2: out = C (raw)
// W / bias / out selected by blockIdx.y.
// ---------------------------------------------------------------------------
__global__ __launch_bounds__(256, 2)
void k_gemm_bf16(const __nv_bfloat16* __restrict__ Ah,
                 const __nv_bfloat16* __restrict__ Al,
                 const __nv_bfloat16* __restrict__ Wh_a,
                 const __nv_bfloat16* __restrict__ Wl_a,
                 const __nv_bfloat16* __restrict__ Wh_b,
                 const __nv_bfloat16* __restrict__ Wl_b,
                 const float* __restrict__ bias_a,
                 const float* __restrict__ bias_b,
                 float* __restrict__ out_a, float* __restrict__ out_b,
                 int N, int K, int ldts, int mode)
{
    extern __shared__ __align__(16) unsigned char dynsmem[];
    __nv_bfloat16* sbase = (__nv_bfloat16*)dynsmem;
    __nv_bfloat16* AhS = sbase;                     // [2][ASZ]
    __nv_bfloat16* AlS = sbase + 2 * ASZ;
    __nv_bfloat16* BhS = sbase + 4 * ASZ;           // [2][BSZ]
    __nv_bfloat16* BlS = sbase + 4 * ASZ + 2 * BSZ;
    float*         stage = (float*)dynsmem;         // epilogue reuse

    const __nv_bfloat16* Wh = blockIdx.y ? Wh_b : Wh_a;
    const __nv_bfloat16* Wl = blockIdx.y ? Wl_b : Wl_a;
    const float* bias = blockIdx.y ? bias_b : bias_a;
    float* outp = blockIdx.y ? out_b : out_a;

    const int tid  = threadIdx.x;
    const int wid  = tid >> 5;
    const int lane = tid & 31;
    const int wm   = wid >> 1;
    const int wn   = wid & 1;
    const int row0 = blockIdx.x * 128;

    const int ar  = tid >> 1;
    const int ac  = (tid & 1) * 16;
    const int br  = tid >> 3;
    const int bc  = (tid & 7) * 16;

    const uint32_t sAh = (uint32_t)__cvta_generic_to_shared(AhS);
    const uint32_t sAl = (uint32_t)__cvta_generic_to_shared(AlS);
    const uint32_t sBh = (uint32_t)__cvta_generic_to_shared(BhS);
    const uint32_t sBl = (uint32_t)__cvta_generic_to_shared(BlS);

    const __nv_bfloat16* gAh = Ah + (size_t)(row0 + ar) * K + ac;
    const __nv_bfloat16* gAl = Al + (size_t)(row0 + ar) * K + ac;
    const __nv_bfloat16* gBh = Wh + (size_t)br * 128 + bc;
    const __nv_bfloat16* gBl = Wl + (size_t)br * 128 + bc;
    const uint32_t aoff = (uint32_t)(ar * A_PITCH + ac) * 2;
    const uint32_t boff = (uint32_t)(br * B_PITCH + bc) * 2;

    wmma::fragment<wmma::accumulator, 16, 16, 16, float> c[2][4];
    #pragma unroll
    for (int mi = 0; mi < 2; mi++)
        #pragma unroll
        for (int ni = 0; ni < 4; ni++)
            wmma::fill_fragment(c[mi][ni], 0.0f);

    const int T = K >> 5;

    auto load_tile = [&](int k0, int b) {
        uint32_t ab = (uint32_t)(b * ASZ) * 2 + aoff;
        uint32_t bb = (uint32_t)(b * BSZ) * 2 + boff;
        cp16(sAh + ab,      gAh + k0);
        cp16(sAh + ab + 16, gAh + k0 + 8);
        cp16(sAl + ab,      gAl + k0);
        cp16(sAl + ab + 16, gAl + k0 + 8);
        cp16(sBh + bb,      gBh + (size_t)k0 * 128);
        cp16(sBh + bb + 16, gBh + (size_t)k0 * 128 + 8);
        cp16(sBl + bb,      gBl + (size_t)k0 * 128);
        cp16(sBl + bb + 16, gBl + (size_t)k0 * 128 + 8);
    };

    load_tile(0, 0);
    CP_COMMIT();

    int buf = 0;
    for (int t = 0; t < T; t++) {
        CP_WAIT_ALL();
        __syncthreads();
        if (t + 1 < T) { load_tile((t + 1) << 5, buf ^ 1); CP_COMMIT(); }

        const __nv_bfloat16* Ah_b = AhS + buf * ASZ;
        const __nv_bfloat16* Al_b = AlS + buf * ASZ;
        const __nv_bfloat16* Bh_b = BhS + buf * BSZ;
        const __nv_bfloat16* Bl_b = BlS + buf * BSZ;

        #pragma unroll
        for (int kk = 0; kk < 32; kk += 16) {
            wmma::fragment<wmma::matrix_a, 16, 16, 16, __nv_bfloat16,
                           wmma::row_major> fah[2], fal[2];
            #pragma unroll
            for (int mi = 0; mi < 2; mi++) {
                wmma::load_matrix_sync(fah[mi],
                    Ah_b + (wm * 32 + mi * 16) * A_PITCH + kk, A_PITCH);
                wmma::load_matrix_sync(fal[mi],
                    Al_b + (wm * 32 + mi * 16) * A_PITCH + kk, A_PITCH);
            }
            #pragma unroll
            for (int ni = 0; ni < 4; ni++) {
                wmma::fragment<wmma::matrix_b, 16, 16, 16, __nv_bfloat16,
                               wmma::row_major> fbh, fbl;
                wmma::load_matrix_sync(fbh,
                    Bh_b + kk * B_PITCH + wn * 64 + ni * 16, B_PITCH);
                wmma::load_matrix_sync(fbl,
                    Bl_b + kk * B_PITCH + wn * 64 + ni * 16, B_PITCH);
                #pragma unroll
                for (int mi = 0; mi < 2; mi++) {
                    wmma::mma_sync(c[mi][ni], fah[mi], fbh, c[mi][ni]);
                    wmma::mma_sync(c[mi][ni], fal[mi], fbh, c[mi][ni]);
                    wmma::mma_sync(c[mi][ni], fah[mi], fbl, c[mi][ni]);
                }
            }
        }
        buf ^= 1;
    }
    __syncthreads();

    float* my_stage = stage + wid * 16 * 20;
    const int srow  = lane >> 1;
    const int shalf = (lane & 1) * 8;
    #pragma unroll
    for (int mi = 0; mi < 2; mi++) {
        #pragma unroll
        for (int ni = 0; ni < 4; ni++) {
            wmma::store_matrix_sync(my_stage, c[mi][ni], 20, wmma::mem_row_major);
            __syncwarp();
            int gr = row0 + wm * 32 + mi * 16 + srow;
            if (gr < N) {
                int ccol = wn * 64 + ni * 16 + shalf;
                float4 v0 = *(float4*)(my_stage + srow * 20 + shalf);
                float4 v1 = *(float4*)(my_stage + srow * 20 + shalf + 4);
                if (mode == 1) {
                    float4 b0 = *(const float4*)(bias + ccol);
                    float4 b1 = *(const float4*)(bias + ccol + 4);
                    v0.x += b0.x; v0.y += b0.y; v0.z += b0.z; v0.w += b0.w;
                    v1.x += b1.x; v1.y += b1.y; v1.z += b1.z; v1.w += b1.w;
                }
                float* dstp = outp + (size_t)gr * ldts + ccol;
                *(float4*)dstp       = v0;
                *(float4*)(dstp + 4) = v1;
            }
            __syncwarp();
        }
    }
}

// ---------------------------------------------------------------------------
// Layer-1 aggregation (warp per node), raw ts (dinv applied here), x4 unroll:
//   hsc = dinv[d] * relu( dinv[d]*( dinv[d]*ts[d] + sum_s dinv[s]*ts[s] ) + b1 )
// ---------------------------------------------------------------------------
__global__ __launch_bounds__(256)
void k_agg1(const float* __restrict__ ts, const int* __restrict__ adj,
            const int* __restrict__ base, const int* __restrict__ deg,
            const float* __restrict__ dinv, const float* __restrict__ b,
            float* __restrict__ hsc, int N)
{
    int node = (blockIdx.x * blockDim.x + threadIdx.x) >> 5;
    int lane = threadIdx.x & 31;
    if (node >= N) return;

    float di = __ldg(&dinv[node]);
    float4 sv = __ldg((const float4*)(ts + (size_t)node * 128) + lane);
    float4 acc;
    acc.x = sv.x * di; acc.y = sv.y * di; acc.z = sv.z * di; acc.w = sv.w * di;

    int e0 = base[node], cnt = deg[node];
    for (int eb = 0; eb < cnt; eb += 32) {
        int rem = cnt - eb;
        int myidx = (lane < rem) ? __ldg(&adj[e0 + eb + lane]) : 0;
        int m = rem < 32 ? rem : 32;
        int j = 0;
        for (; j + 4 <= m; j += 4) {
            int s0 = __shfl_sync(0xffffffffu, myidx, j);
            int s1 = __shfl_sync(0xffffffffu, myidx, j + 1);
            int s2 = __shfl_sync(0xffffffffu, myidx, j + 2);
            int s3 = __shfl_sync(0xffffffffu, myidx, j + 3);
            float w0 = __ldg(&dinv[s0]);
            float w1 = __ldg(&dinv[s1]);
            float w2 = __ldg(&dinv[s2]);
            float w3 = __ldg(&dinv[s3]);
            float4 v0 = __ldg((const float4*)(ts + (size_t)s0 * 128) + lane);
            float4 v1 = __ldg((const float4*)(ts + (size_t)s1 * 128) + lane);
            float4 v2 = __ldg((const float4*)(ts + (size_t)s2 * 128) + lane);
            float4 v3 = __ldg((const float4*)(ts + (size_t)s3 * 128) + lane);
            acc.x = fmaf(v0.x, w0, acc.x); acc.y = fmaf(v0.y, w0, acc.y);
            acc.z = fmaf(v0.z, w0, acc.z); acc.w = fmaf(v0.w, w0, acc.w);
            acc.x = fmaf(v1.x, w1, acc.x); acc.y = fmaf(v1.y, w1, acc.y);
            acc.z = fmaf(v1.z, w1, acc.z); acc.w = fmaf(v1.w, w1, acc.w);
            acc.x = fmaf(v2.x, w2, acc.x); acc.y = fmaf(v2.y, w2, acc.y);
            acc.z = fmaf(v2.z, w2, acc.z); acc.w = fmaf(v2.w, w2, acc.w);
            acc.x = fmaf(v3.x, w3, acc.x); acc.y = fmaf(v3.y, w3, acc.y);
            acc.z = fmaf(v3.z, w3, acc.z); acc.w = fmaf(v3.w, w3, acc.w);
        }
        for (; j < m; j++) {
            int s = __shfl_sync(0xffffffffu, myidx, j);
            float w = __ldg(&dinv[s]);
            float4 v = __ldg((const float4*)(ts + (size_t)s * 128) + lane);
            acc.x = fmaf(v.x, w, acc.x); acc.y = fmaf(v.y, w, acc.y);
            acc.z = fmaf(v.z, w, acc.z); acc.w = fmaf(v.w, w, acc.w);
        }
    }

    float4 bb = __ldg((const float4*)b + lane);
    float4 o;
    o.x = di * fmaxf(fmaf(acc.x, di, bb.x), 0.f);
    o.y = di * fmaxf(fmaf(acc.y, di, bb.y), 0.f);
    o.z = di * fmaxf(fmaf(acc.z, di, bb.z), 0.f);
    o.w = di * fmaxf(fmaf(acc.w, di, bb.w), 0.f);
    ((float4*)(hsc + (size_t)node * 128))[lane] = o;
}

// ---------------------------------------------------------------------------
// Layer-2 pre-GEMM aggregation (warp per node), x4 unroll:
//   hagg = dinv[d]*( hsc[d] + sum_s hsc[s] )  -> bf16 hi/lo
// ---------------------------------------------------------------------------
__global__ __launch_bounds__(256)
void k_agg2(const float* __restrict__ hsc, const int* __restrict__ adj,
            const int* __restrict__ base, const int* __restrict__ deg,
            const float* __restrict__ dinv,
            __nv_bfloat16* __restrict__ ah, __nv_bfloat16* __restrict__ al,
            int N)
{
    int node = (blockIdx.x * blockDim.x + threadIdx.x) >> 5;
    int lane = threadIdx.x & 31;
    if (node >= N) return;

    float4 acc = __ldg((const float4*)(hsc + (size_t)node * 128) + lane);
    int e0 = base[node], cnt = deg[node];

    for (int eb = 0; eb < cnt; eb += 32) {
        int rem = cnt - eb;
        int myidx = (lane < rem) ? __ldg(&adj[e0 + eb + lane]) : 0;
        int m = rem < 32 ? rem : 32;
        int j = 0;
        for (; j + 4 <= m; j += 4) {
            int s0 = __shfl_sync(0xffffffffu, myidx, j);
            int s1 = __shfl_sync(0xffffffffu, myidx, j + 1);
            int s2 = __shfl_sync(0xffffffffu, myidx, j + 2);
            int s3 = __shfl_sync(0xffffffffu, myidx, j + 3);
            float4 v0 = __ldg((const float4*)(hsc + (size_t)s0 * 128) + lane);
            float4 v1 = __ldg((const float4*)(hsc + (size_t)s1 * 128) + lane);
            float4 v2 = __ldg((const float4*)(hsc + (size_t)s2 * 128) + lane);
            float4 v3 = __ldg((const float4*)(hsc + (size_t)s3 * 128) + lane);
            acc.x += v0.x + v1.x + v2.x + v3.x;
            acc.y += v0.y + v1.y + v2.y + v3.y;
            acc.z += v0.z + v1.z + v2.z + v3.z;
            acc.w += v0.w + v1.w + v2.w + v3.w;
        }
        for (; j < m; j++) {
            int s = __shfl_sync(0xffffffffu, myidx, j);
            float4 v = __ldg((const float4*)(hsc + (size_t)s * 128) + lane);
            acc.x += v.x; acc.y += v.y; acc.z += v.z; acc.w += v.w;
        }
    }

    float di = dinv[node];
    acc.x *= di; acc.y *= di; acc.z *= di; acc.w *= di;

    __nv_bfloat16 hx = __float2bfloat16(acc.x);
    __nv_bfloat16 hy = __float2bfloat16(acc.y);
    __nv_bfloat16 hz = __float2bfloat16(acc.z);
    __nv_bfloat16 hw = __float2bfloat16(acc.w);
    __nv_bfloat162* hp = (__nv_bfloat162*)(ah + (size_t)node * 128) + lane * 2;
    __nv_bfloat162* lp = (__nv_bfloat162*)(al + (size_t)node * 128) + lane * 2;
    hp[0] = __nv_bfloat162(hx, hy);
    hp[1] = __nv_bfloat162(hz, hw);
    lp[0] = __nv_bfloat162(__float2bfloat16(acc.x - __bfloat162float(hx)),
                           __float2bfloat16(acc.y - __bfloat162float(hy)));
    lp[1] = __nv_bfloat162(__float2bfloat16(acc.z - __bfloat162float(hz)),
                           __float2bfloat16(acc.w - __bfloat162float(hw)));
}

// ---------------------------------------------------------------------------

extern "C" void kernel_launch(void* const* d_in, const int* in_sizes, int n_in,
                              void* d_out, int out_size)
{
    const float* x   = (const float*)d_in[0];
    const int*   ei  = (const int*)  d_in[1];
    const float* W1  = (const float*)d_in[2];
    const float* b1  = (const float*)d_in[3];
    const float* Wmu = (const float*)d_in[4];
    const float* bmu = (const float*)d_in[5];
    const float* Wls = (const float*)d_in[6];
    const float* bls = (const float*)d_in[7];

    const int N = in_sizes[0] / 256;   // C_in = 256
    const int E = in_sizes[1] / 2;
    const int* src = ei;
    const int* dst = ei + E;

    float* out = (float*)d_out;
    float* mu  = out;
    float* ls  = out + (size_t)N * HDIM;

    int *deg, *base, *cursor, *part, *adj;
    float *dinv, *ts1, *hsc;
    __nv_bfloat16 *ah, *al, *wh, *wl;
    cudaGetSymbolAddress((void**)&deg,    g_deg);
    cudaGetSymbolAddress((void**)&base,   g_base);
    cudaGetSymbolAddress((void**)&cursor, g_cursor);
    cudaGetSymbolAddress((void**)&part,   g_part);
    cudaGetSymbolAddress((void**)&adj,    g_adj);
    cudaGetSymbolAddress((void**)&dinv,   g_dinv);
    cudaGetSymbolAddress((void**)&ts1,    g_ts1);
    cudaGetSymbolAddress((void**)&hsc,    g_hsc);
    cudaGetSymbolAddress((void**)&ah,     g_ah);
    cudaGetSymbolAddress((void**)&al,     g_al);
    cudaGetSymbolAddress((void**)&wh,     g_wh);
    cudaGetSymbolAddress((void**)&wl,     g_wl);

    cudaFuncSetAttribute(k_gemm_bf16,
                         cudaFuncAttributeMaxDynamicSharedMemorySize, GEMM_SMEM);

    // side stream + fork/join events, created once on the first
    // (uncaptured) call; reused identically on every call thereafter.
    static cudaStream_t sB = nullptr;
    static cudaEvent_t  evFork = nullptr, evJoin = nullptr, evW = nullptr;
    if (sB == nullptr) {
        cudaStreamCreateWithFlags(&sB, cudaStreamNonBlocking);
        cudaEventCreateWithFlags(&evFork, cudaEventDisableTiming);
        cudaEventCreateWithFlags(&evJoin, cudaEventDisableTiming);
        cudaEventCreateWithFlags(&evW,    cudaEventDisableTiming);
    }

    const int nb   = (N + 255) / 256;
    const int eb   = (E + 255) / 256;
    const int gb   = (N + 127) / 128;
    const int sbnk = (N + SCAN_B - 1) / SCAN_B;
    const int ab   = (N * 32 + 255) / 256;

    // ---- fork: split_w + CSR build on stream B ---------------------------
    cudaEventRecord(evFork, 0);
    cudaStreamWaitEvent(sB, evFork, 0);
    k_split_w   <<<(16384 + 255) / 256, 256, 0, sB>>>(W1, Wmu, Wls, wh, wl);
    cudaEventRecord(evW, sB);
    k_zero_int  <<<nb, 256, 0, sB>>>(deg, N);
    k_count     <<<eb, 256, 0, sB>>>(dst, deg, E);
    k_scan_block<<<sbnk, SCAN_B, 0, sB>>>(deg, base, part, N);
    k_scan_part <<<1, 64, 0, sB>>>(part, sbnk);
    k_scan_add  <<<sbnk, SCAN_B, 0, sB>>>(base, cursor, part, deg, dinv, N);
    k_fill      <<<eb, 256, 0, sB>>>(src, dst, cursor, adj, E);
    cudaEventRecord(evJoin, sB);

    // ---- default stream: split(x), then GEMM1 (raw; waits on weights) ----
    {
        int n4 = N * 256 / 4;
        k_split<<<(n4 + 255) / 256, 256>>>(x, ah, al, n4);
    }
    cudaStreamWaitEvent(0, evW, 0);
    k_gemm_bf16<<<dim3(gb, 1), 256, GEMM_SMEM>>>(ah, al, wh, wl, wh, wl,
                                                 nullptr, nullptr,
                                                 ts1, ts1, N, 256, 128, 2);

    // ---- join, then serial tail -----------------------------------------
    cudaStreamWaitEvent(0, evJoin, 0);
    k_agg1<<<ab, 256>>>(ts1, adj, base, deg, dinv, b1, hsc, N);
    k_agg2<<<ab, 256>>>(hsc, adj, base, deg, dinv, ah, al, N);
    k_gemm_bf16<<<dim3(gb, 2), 256, GEMM_SMEM>>>(ah, al,
                                                 wh + 256 * 128, wl + 256 * 128,
                                                 wh + 384 * 128, wl + 384 * 128,
                                                 bmu, bls,
                                                 mu, ls, N, 128, 128, 1);
}

// round 17
// speedup vs baseline: 1.4611x; 1.4611x over previous
#include <cuda_runtime.h>
#include <cuda_bf16.h>
#include <mma.h>
#include <cstdint>

using namespace nvcuda;

// ---------------------------------------------------------------------------
// Stochastic_encoder (VGAE GCN encoder), bf16 split-precision wmma GEMMs,
// cp.async double-buffered mainloop, forked capture graph:
//   stream B: split_w, CSR build (zero/count/scan/fill + dinv)
//   default : split(x), GEMM1 (raw x@W1, waits only on split_w)
//   join    : agg1 (applies dinv weights) -> agg2 -> GEMM2 -> d_out
// ---------------------------------------------------------------------------

#define NMAX   50176
#define EMAX   800000
#define HDIM   128
#define SCAN_B 1024
#define A_PITCH 40
#define B_PITCH 136
#define ASZ (128 * A_PITCH)   // 5120 bf16 per A buffer
#define BSZ (32 * B_PITCH)    // 4352 bf16 per B buffer
#define GEMM_SMEM ((4 * ASZ + 4 * BSZ) * 2)   // 75776 bytes

__device__ int   g_deg   [NMAX];
__device__ int   g_base  [NMAX];
__device__ int   g_cursor[NMAX];
__device__ int   g_part  [256];
__device__ int   g_adj   [EMAX];
__device__ float g_dinv  [NMAX];
__device__ float g_ts1   [(size_t)NMAX * HDIM];
__device__ float g_hsc   [(size_t)NMAX * HDIM];

__device__ __nv_bfloat16 g_ah[(size_t)NMAX * 256];
__device__ __nv_bfloat16 g_al[(size_t)NMAX * 256];
__device__ __nv_bfloat16 g_wh[512 * 128];   // W1 @0 (256 rows), Wmu @256, Wls @384
__device__ __nv_bfloat16 g_wl[512 * 128];

// --- cp.async helpers ------------------------------------------------------
__device__ __forceinline__ void cp16(uint32_t sdst, const void* gsrc) {
    asm volatile("cp.async.cg.shared.global [%0], [%1], 16;"
                 :: "r"(sdst), "l"(gsrc));
}
#define CP_COMMIT()   asm volatile("cp.async.commit_group;" ::: "memory")
#define CP_WAIT_ALL() asm volatile("cp.async.wait_group 0;" ::: "memory")

// ---------------------------------------------------------------------------

__global__ void k_zero_int(int* __restrict__ p, int n) {
    int i = blockIdx.x * blockDim.x + threadIdx.x;
    if (i < n) p[i] = 0;
}

__global__ void k_count(const int* __restrict__ dst, int* __restrict__ deg, int E) {
    int i = blockIdx.x * blockDim.x + threadIdx.x;
    if (i < E) atomicAdd(&deg[dst[i]], 1);
}

__global__ void k_scan_block(const int* __restrict__ deg, int* __restrict__ base,
                             int* __restrict__ part, int n)
{
    __shared__ int sh[SCAN_B];
    int gi = blockIdx.x * SCAN_B + threadIdx.x;
    int v = (gi < n) ? deg[gi] : 0;
    sh[threadIdx.x] = v;
    __syncthreads();
    #pragma unroll
    for (int off = 1; off < SCAN_B; off <<= 1) {
        int t = (threadIdx.x >= off) ? sh[threadIdx.x - off] : 0;
        __syncthreads();
        sh[threadIdx.x] += t;
        __syncthreads();
    }
    if (gi < n) base[gi] = sh[threadIdx.x] - v;
    if (threadIdx.x == SCAN_B - 1) part[blockIdx.x] = sh[threadIdx.x];
}

__global__ void k_scan_part(int* __restrict__ part, int nb) {
    __shared__ int sh[64];
    int i = threadIdx.x;
    int v = (i < nb) ? part[i] : 0;
    sh[i] = v;
    __syncthreads();
    #pragma unroll
    for (int off = 1; off < 64; off <<= 1) {
        int t = (i >= off) ? sh[i - off] : 0;
        __syncthreads();
        sh[i] += t;
        __syncthreads();
    }
    if (i < nb) part[i] = sh[i] - v;   // exclusive
}

__global__ void k_scan_add(int* __restrict__ base, int* __restrict__ cursor,
                           const int* __restrict__ part,
                           const int* __restrict__ deg,
                           float* __restrict__ dinv, int n) {
    int gi = blockIdx.x * SCAN_B + threadIdx.x;
    if (gi < n) {
        int b = base[gi] + part[blockIdx.x];
        base[gi]   = b;
        cursor[gi] = b;
        dinv[gi]   = rsqrtf((float)deg[gi] + 1.0f);
    }
}

__global__ void k_fill(const int* __restrict__ src, const int* __restrict__ dst,
                       int* __restrict__ cursor, int* __restrict__ adj, int E)
{
    int i = blockIdx.x * blockDim.x + threadIdx.x;
    if (i < E) {
        int pos = atomicAdd(&cursor[dst[i]], 1);
        adj[pos] = src[i];
    }
}

// ---------------------------------------------------------------------------
// fp32 -> bf16 (hi, lo) split, vectorized x4.
// ---------------------------------------------------------------------------
__device__ __forceinline__ void split_store(float4 v,
                                            __nv_bfloat16* hi,
                                            __nv_bfloat16* lo, int i)
{
    __nv_bfloat16 hx = __float2bfloat16(v.x);
    __nv_bfloat16 hy = __float2bfloat16(v.y);
    __nv_bfloat16 hz = __float2bfloat16(v.z);
    __nv_bfloat16 hw = __float2bfloat16(v.w);
    __nv_bfloat162* hp = (__nv_bfloat162*)hi;
    __nv_bfloat162* lp = (__nv_bfloat162*)lo;
    hp[2 * i]     = __nv_bfloat162(hx, hy);
    hp[2 * i + 1] = __nv_bfloat162(hz, hw);
    lp[2 * i]     = __nv_bfloat162(__float2bfloat16(v.x - __bfloat162float(hx)),
                                   __float2bfloat16(v.y - __bfloat162float(hy)));
    lp[2 * i + 1] = __nv_bfloat162(__float2bfloat16(v.z - __bfloat162float(hz)),
                                   __float2bfloat16(v.w - __bfloat162float(hw)));
}

__global__ void k_split(const float* __restrict__ src,
                        __nv_bfloat16* __restrict__ hi,
                        __nv_bfloat16* __restrict__ lo, int n4)
{
    int i = blockIdx.x * blockDim.x + threadIdx.x;
    if (i < n4) split_store(((const float4*)src)[i], hi, lo, i);
}

__global__ void k_split_w(const float* __restrict__ W1,
                          const float* __restrict__ Wmu,
                          const float* __restrict__ Wls,
                          __nv_bfloat16* __restrict__ wh,
                          __nv_bfloat16* __restrict__ wl)
{
    int i = blockIdx.x * blockDim.x + threadIdx.x;   // float4 index, < 16384
    if (i < 8192) {
        split_store(((const float4*)W1)[i], wh, wl, i);
    } else if (i < 12288) {
        int j = i - 8192;
        split_store(((const float4*)Wmu)[j], wh + 256 * 128, wl + 256 * 128, j);
    } else if (i < 16384) {
        int j = i - 12288;
        split_store(((const float4*)Wls)[j], wh + 384 * 128, wl + 384 * 128, j);
    }
}

// ---------------------------------------------------------------------------
// bf16 split-precision wmma GEMM, cp.async double-buffered.
//   C = Ah*Wh + Al*Wh + Ah*Wl (fp32 accum)
// mode 1: out = C + bias[c]   mode 2: out = C (raw)
// W / bias / out selected by blockIdx.y.
// ---------------------------------------------------------------------------
__global__ __launch_bounds__(256, 2)
void k_gemm_bf16(const __nv_bfloat16* __restrict__ Ah,
                 const __nv_bfloat16* __restrict__ Al,
                 const __nv_bfloat16* __restrict__ Wh_a,
                 const __nv_bfloat16* __restrict__ Wl_a,
                 const __nv_bfloat16* __restrict__ Wh_b,
                 const __nv_bfloat16* __restrict__ Wl_b,
                 const float* __restrict__ bias_a,
                 const float* __restrict__ bias_b,
                 float* __restrict__ out_a, float* __restrict__ out_b,
                 int N, int K, int ldts, int mode)
{
    extern __shared__ __align__(16) unsigned char dynsmem[];
    __nv_bfloat16* sbase = (__nv_bfloat16*)dynsmem;
    __nv_bfloat16* AhS = sbase;                     // [2][ASZ]
    __nv_bfloat16* AlS = sbase + 2 * ASZ;
    __nv_bfloat16* BhS = sbase + 4 * ASZ;           // [2][BSZ]
    __nv_bfloat16* BlS = sbase + 4 * ASZ + 2 * BSZ;
    float*         stage = (float*)dynsmem;         // epilogue reuse

    const __nv_bfloat16* Wh = blockIdx.y ? Wh_b : Wh_a;
    const __nv_bfloat16* Wl = blockIdx.y ? Wl_b : Wl_a;
    const float* bias = blockIdx.y ? bias_b : bias_a;
    float* outp = blockIdx.y ? out_b : out_a;

    const int tid  = threadIdx.x;
    const int wid  = tid >> 5;
    const int lane = tid & 31;
    const int wm   = wid >> 1;
    const int wn   = wid & 1;
    const int row0 = blockIdx.x * 128;

    const int ar  = tid >> 1;
    const int ac  = (tid & 1) * 16;
    const int br  = tid >> 3;
    const int bc  = (tid & 7) * 16;

    const uint32_t sAh = (uint32_t)__cvta_generic_to_shared(AhS);
    const uint32_t sAl = (uint32_t)__cvta_generic_to_shared(AlS);
    const uint32_t sBh = (uint32_t)__cvta_generic_to_shared(BhS);
    const uint32_t sBl = (uint32_t)__cvta_generic_to_shared(BlS);

    const __nv_bfloat16* gAh = Ah + (size_t)(row0 + ar) * K + ac;
    const __nv_bfloat16* gAl = Al + (size_t)(row0 + ar) * K + ac;
    const __nv_bfloat16* gBh = Wh + (size_t)br * 128 + bc;
    const __nv_bfloat16* gBl = Wl + (size_t)br * 128 + bc;
    const uint32_t aoff = (uint32_t)(ar * A_PITCH + ac) * 2;
    const uint32_t boff = (uint32_t)(br * B_PITCH + bc) * 2;

    wmma::fragment<wmma::accumulator, 16, 16, 16, float> c[2][4];
    #pragma unroll
    for (int mi = 0; mi < 2; mi++)
        #pragma unroll
        for (int ni = 0; ni < 4; ni++)
            wmma::fill_fragment(c[mi][ni], 0.0f);

    const int T = K >> 5;

    auto load_tile = [&](int k0, int b) {
        uint32_t ab = (uint32_t)(b * ASZ) * 2 + aoff;
        uint32_t bb = (uint32_t)(b * BSZ) * 2 + boff;
        cp16(sAh + ab,      gAh + k0);
        cp16(sAh + ab + 16, gAh + k0 + 8);
        cp16(sAl + ab,      gAl + k0);
        cp16(sAl + ab + 16, gAl + k0 + 8);
        cp16(sBh + bb,      gBh + (size_t)k0 * 128);
        cp16(sBh + bb + 16, gBh + (size_t)k0 * 128 + 8);
        cp16(sBl + bb,      gBl + (size_t)k0 * 128);
        cp16(sBl + bb + 16, gBl + (size_t)k0 * 128 + 8);
    };

    load_tile(0, 0);
    CP_COMMIT();

    int buf = 0;
    for (int t = 0; t < T; t++) {
        CP_WAIT_ALL();
        __syncthreads();
        if (t + 1 < T) { load_tile((t + 1) << 5, buf ^ 1); CP_COMMIT(); }

        const __nv_bfloat16* Ah_b = AhS + buf * ASZ;
        const __nv_bfloat16* Al_b = AlS + buf * ASZ;
        const __nv_bfloat16* Bh_b = BhS + buf * BSZ;
        const __nv_bfloat16* Bl_b = BlS + buf * BSZ;

        #pragma unroll
        for (int kk = 0; kk < 32; kk += 16) {
            wmma::fragment<wmma::matrix_a, 16, 16, 16, __nv_bfloat16,
                           wmma::row_major> fah[2], fal[2];
            #pragma unroll
            for (int mi = 0; mi < 2; mi++) {
                wmma::load_matrix_sync(fah[mi],
                    Ah_b + (wm * 32 + mi * 16) * A_PITCH + kk, A_PITCH);
                wmma::load_matrix_sync(fal[mi],
                    Al_b + (wm * 32 + mi * 16) * A_PITCH + kk, A_PITCH);
            }
            #pragma unroll
            for (int ni = 0; ni < 4; ni++) {
                wmma::fragment<wmma::matrix_b, 16, 16, 16, __nv_bfloat16,
                               wmma::row_major> fbh, fbl;
                wmma::load_matrix_sync(fbh,
                    Bh_b + kk * B_PITCH + wn * 64 + ni * 16, B_PITCH);
                wmma::load_matrix_sync(fbl,
                    Bl_b + kk * B_PITCH + wn * 64 + ni * 16, B_PITCH);
                #pragma unroll
                for (int mi = 0; mi < 2; mi++) {
                    wmma::mma_sync(c[mi][ni], fah[mi], fbh, c[mi][ni]);
                    wmma::mma_sync(c[mi][ni], fal[mi], fbh, c[mi][ni]);
                    wmma::mma_sync(c[mi][ni], fah[mi], fbl, c[mi][ni]);
                }
            }
        }
        buf ^= 1;
    }
    __syncthreads();

    float* my_stage = stage + wid * 16 * 20;
    const int srow  = lane >> 1;
    const int shalf = (lane & 1) * 8;
    #pragma unroll
    for (int mi = 0; mi < 2; mi++) {
        #pragma unroll
        for (int ni = 0; ni < 4; ni++) {
            wmma::store_matrix_sync(my_stage, c[mi][ni], 20, wmma::mem_row_major);
            __syncwarp();
            int gr = row0 + wm * 32 + mi * 16 + srow;
            if (gr < N) {
                int ccol = wn * 64 + ni * 16 + shalf;
                float4 v0 = *(float4*)(my_stage + srow * 20 + shalf);
                float4 v1 = *(float4*)(my_stage + srow * 20 + shalf + 4);
                if (mode == 1) {
                    float4 b0 = *(const float4*)(bias + ccol);
                    float4 b1 = *(const float4*)(bias + ccol + 4);
                    v0.x += b0.x; v0.y += b0.y; v0.z += b0.z; v0.w += b0.w;
                    v1.x += b1.x; v1.y += b1.y; v1.z += b1.z; v1.w += b1.w;
                }
                float* dstp = outp + (size_t)gr * ldts + ccol;
                *(float4*)dstp       = v0;
                *(float4*)(dstp + 4) = v1;
            }
            __syncwarp();
        }
    }
}

// ---------------------------------------------------------------------------
// Layer-1 aggregation (warp per node), raw ts (dinv applied here):
//   hsc = dinv[d] * relu( dinv[d]*( dinv[d]*ts[d] + sum_s dinv[s]*ts[s] ) + b1 )
// ---------------------------------------------------------------------------
__global__ __launch_bounds__(256)
void k_agg1(const float* __restrict__ ts, const int* __restrict__ adj,
            const int* __restrict__ base, const int* __restrict__ deg,
            const float* __restrict__ dinv, const float* __restrict__ b,
            float* __restrict__ hsc, int N)
{
    int node = (blockIdx.x * blockDim.x + threadIdx.x) >> 5;
    int lane = threadIdx.x & 31;
    if (node >= N) return;

    float di = __ldg(&dinv[node]);
    float4 sv = __ldg((const float4*)(ts + (size_t)node * 128) + lane);
    float4 acc;
    acc.x = sv.x * di; acc.y = sv.y * di; acc.z = sv.z * di; acc.w = sv.w * di;

    int e0 = base[node], cnt = deg[node];
    for (int eb = 0; eb < cnt; eb += 32) {
        int rem = cnt - eb;
        int myidx = (lane < rem) ? __ldg(&adj[e0 + eb + lane]) : 0;
        int m = rem < 32 ? rem : 32;
        for (int j = 0; j < m; j++) {
            int s = __shfl_sync(0xffffffffu, myidx, j);
            float w = __ldg(&dinv[s]);
            float4 v = __ldg((const float4*)(ts + (size_t)s * 128) + lane);
            acc.x = fmaf(v.x, w, acc.x); acc.y = fmaf(v.y, w, acc.y);
            acc.z = fmaf(v.z, w, acc.z); acc.w = fmaf(v.w, w, acc.w);
        }
    }

    float4 bb = __ldg((const float4*)b + lane);
    float4 o;
    o.x = di * fmaxf(fmaf(acc.x, di, bb.x), 0.f);
    o.y = di * fmaxf(fmaf(acc.y, di, bb.y), 0.f);
    o.z = di * fmaxf(fmaf(acc.z, di, bb.z), 0.f);
    o.w = di * fmaxf(fmaf(acc.w, di, bb.w), 0.f);
    ((float4*)(hsc + (size_t)node * 128))[lane] = o;
}

// ---------------------------------------------------------------------------
// Layer-2 pre-GEMM aggregation (warp per node):
//   hagg = dinv[d]*( hsc[d] + sum_s hsc[s] )  -> bf16 hi/lo
// ---------------------------------------------------------------------------
__global__ __launch_bounds__(256)
void k_agg2(const float* __restrict__ hsc, const int* __restrict__ adj,
            const int* __restrict__ base, const int* __restrict__ deg,
            const float* __restrict__ dinv,
            __nv_bfloat16* __restrict__ ah, __nv_bfloat16* __restrict__ al,
            int N)
{
    int node = (blockIdx.x * blockDim.x + threadIdx.x) >> 5;
    int lane = threadIdx.x & 31;
    if (node >= N) return;

    float4 acc = __ldg((const float4*)(hsc + (size_t)node * 128) + lane);
    int e0 = base[node], cnt = deg[node];

    for (int eb = 0; eb < cnt; eb += 32) {
        int rem = cnt - eb;
        int myidx = (lane < rem) ? __ldg(&adj[e0 + eb + lane]) : 0;
        int m = rem < 32 ? rem : 32;
        for (int j = 0; j < m; j++) {
            int s = __shfl_sync(0xffffffffu, myidx, j);
            float4 v = __ldg((const float4*)(hsc + (size_t)s * 128) + lane);
            acc.x += v.x; acc.y += v.y; acc.z += v.z; acc.w += v.w;
        }
    }

    float di = dinv[node];
    acc.x *= di; acc.y *= di; acc.z *= di; acc.w *= di;

    __nv_bfloat16 hx = __float2bfloat16(acc.x);
    __nv_bfloat16 hy = __float2bfloat16(acc.y);
    __nv_bfloat16 hz = __float2bfloat16(acc.z);
    __nv_bfloat16 hw = __float2bfloat16(acc.w);
    __nv_bfloat162* hp = (__nv_bfloat162*)(ah + (size_t)node * 128) + lane * 2;
    __nv_bfloat162* lp = (__nv_bfloat162*)(al + (size_t)node * 128) + lane * 2;
    hp[0] = __nv_bfloat162(hx, hy);
    hp[1] = __nv_bfloat162(hz, hw);
    lp[0] = __nv_bfloat162(__float2bfloat16(acc.x - __bfloat162float(hx)),
                           __float2bfloat16(acc.y - __bfloat162float(hy)));
    lp[1] = __nv_bfloat162(__float2bfloat16(acc.z - __bfloat162float(hz)),
                           __float2bfloat16(acc.w - __bfloat162float(hw)));
}

// ---------------------------------------------------------------------------

extern "C" void kernel_launch(void* const* d_in, const int* in_sizes, int n_in,
                              void* d_out, int out_size)
{
    const float* x   = (const float*)d_in[0];
    const int*   ei  = (const int*)  d_in[1];
    const float* W1  = (const float*)d_in[2];
    const float* b1  = (const float*)d_in[3];
    const float* Wmu = (const float*)d_in[4];
    const float* bmu = (const float*)d_in[5];
    const float* Wls = (const float*)d_in[6];
    const float* bls = (const float*)d_in[7];

    const int N = in_sizes[0] / 256;   // C_in = 256
    const int E = in_sizes[1] / 2;
    const int* src = ei;
    const int* dst = ei + E;

    float* out = (float*)d_out;
    float* mu  = out;
    float* ls  = out + (size_t)N * HDIM;

    int *deg, *base, *cursor, *part, *adj;
    float *dinv, *ts1, *hsc;
    __nv_bfloat16 *ah, *al, *wh, *wl;
    cudaGetSymbolAddress((void**)&deg,    g_deg);
    cudaGetSymbolAddress((void**)&base,   g_base);
    cudaGetSymbolAddress((void**)&cursor, g_cursor);
    cudaGetSymbolAddress((void**)&part,   g_part);
    cudaGetSymbolAddress((void**)&adj,    g_adj);
    cudaGetSymbolAddress((void**)&dinv,   g_dinv);
    cudaGetSymbolAddress((void**)&ts1,    g_ts1);
    cudaGetSymbolAddress((void**)&hsc,    g_hsc);
    cudaGetSymbolAddress((void**)&ah,     g_ah);
    cudaGetSymbolAddress((void**)&al,     g_al);
    cudaGetSymbolAddress((void**)&wh,     g_wh);
    cudaGetSymbolAddress((void**)&wl,     g_wl);

    cudaFuncSetAttribute(k_gemm_bf16,
                         cudaFuncAttributeMaxDynamicSharedMemorySize, GEMM_SMEM);

    // side stream + fork/join events, created once on the first
    // (uncaptured) call; reused identically on every call thereafter.
    static cudaStream_t sB = nullptr;
    static cudaEvent_t  evFork = nullptr, evJoin = nullptr, evW = nullptr;
    if (sB == nullptr) {
        cudaStreamCreateWithFlags(&sB, cudaStreamNonBlocking);
        cudaEventCreateWithFlags(&evFork, cudaEventDisableTiming);
        cudaEventCreateWithFlags(&evJoin, cudaEventDisableTiming);
        cudaEventCreateWithFlags(&evW,    cudaEventDisableTiming);
    }

    const int nb   = (N + 255) / 256;
    const int eb   = (E + 255) / 256;
    const int gb   = (N + 127) / 128;
    const int sbnk = (N + SCAN_B - 1) / SCAN_B;
    const int ab   = (N * 32 + 255) / 256;

    // ---- fork: split_w + CSR build on stream B ---------------------------
    cudaEventRecord(evFork, 0);
    cudaStreamWaitEvent(sB, evFork, 0);
    k_split_w   <<<(16384 + 255) / 256, 256, 0, sB>>>(W1, Wmu, Wls, wh, wl);
    cudaEventRecord(evW, sB);
    k_zero_int  <<<nb, 256, 0, sB>>>(deg, N);
    k_count     <<<eb, 256, 0, sB>>>(dst, deg, E);
    k_scan_block<<<sbnk, SCAN_B, 0, sB>>>(deg, base, part, N);
    k_scan_part <<<1, 64, 0, sB>>>(part, sbnk);
    k_scan_add  <<<sbnk, SCAN_B, 0, sB>>>(base, cursor, part, deg, dinv, N);
    k_fill      <<<eb, 256, 0, sB>>>(src, dst, cursor, adj, E);
    cudaEventRecord(evJoin, sB);

    // ---- default stream: split(x), then GEMM1 (raw; waits on weights) ----
    {
        int n4 = N * 256 / 4;
        k_split<<<(n4 + 255) / 256, 256>>>(x, ah, al, n4);
    }
    cudaStreamWaitEvent(0, evW, 0);
    k_gemm_bf16<<<dim3(gb, 1), 256, GEMM_SMEM>>>(ah, al, wh, wl, wh, wl,
                                                 nullptr, nullptr,
                                                 ts1, ts1, N, 256, 128, 2);

    // ---- join, then serial tail -----------------------------------------
    cudaStreamWaitEvent(0, evJoin, 0);
    k_agg1<<<ab, 256>>>(ts1, adj, base, deg, dinv, b1, hsc, N);
    k_agg2<<<ab, 256>>>(hsc, adj, base, deg, dinv, ah, al, N);
    k_gemm_bf16<<<dim3(gb, 2), 256, GEMM_SMEM>>>(ah, al,
                                                 wh + 256 * 128, wl + 256 * 128,
                                                 wh + 384 * 128, wl + 384 * 128,
                                                 bmu, bls,
                                                 mu, ls, N, 128, 128, 1);
}